// round 12
// baseline (speedup 1.0000x reference)
#include <cuda_runtime.h>
#include <cuda_bf16.h>
#include <math.h>

#define TT 1024
#define BB 512
#define KK 128

__device__ float g_negLogZ[BB];   // -logZ per batch (fwd writes, path reads)

// ---- forward recurrence: scaled linear domain, bf16x2 matvec (lanes = i-pairs) ----
// ONE batch per CTA: grid = 512, 128 threads, 4 CTAs/SM -> 4 independent warps/SMSP.
__global__ void __launch_bounds__(128, 4) crf_fwd_kernel(
    const float* __restrict__ em,      // [T,B,K]
    const float* __restrict__ mask,    // [T,B]
    const float* __restrict__ startT,  // [K]
    const float* __restrict__ trans,   // [K,K]
    const float* __restrict__ endT,    // [K]
    float* __restrict__ out)
{
    __shared__ alignas(16) __nv_bfloat16 pv[2][KK];  // [buf][i] state (1 batch)
    __shared__ float wred[4];

    const int j    = threadIdx.x;   // tag column owned by this thread
    const int warp = j >> 5;
    const int lane = j & 31;
    const int b    = blockIdx.x;    // batch owned by this CTA

    if (b == 0 && j == 0) out[0] = 0.0f;  // zero for launch-2 atomics

    // E column packed over i-pairs: epk[m] = (E[2m][j], E[2m+1][j])  -> 64 regs
    __nv_bfloat162 epk[KK / 2];
#pragma unroll
    for (int m = 0; m < KK / 2; m++) {
        epk[m] = __floats2bfloat162_rn(__expf(trans[(2 * m) * KK + j]),
                                       __expf(trans[(2 * m + 1) * KK + j]));
    }

    float u;        // fp32 master state for column j
    int   Ce = 0;   // exact power-of-2 scale exponent
    u = __expf(startT[j] + em[b * KK + j]);
    pv[1][j] = __float2bfloat16(u);   // step t=1 reads buffer 1
    __syncthreads();

    // 2-deep register prefetch pipeline for em/mask
    float ecur  = __ldg(&em[(1 * BB + b) * KK + j]);
    float mcur  = __ldg(&mask[1 * BB + b]);
    float enext = __ldg(&em[(2 * BB + b) * KK + j]);
    float mnext = __ldg(&mask[2 * BB + b]);

    for (int t = 1; t < TT; t++) {
        const int r = t & 1, w = r ^ 1;

        // exp(em) early: MUFU latency hides under the matvec
        const float ex = __expf(ecur);

        // kick off loads for t+2 (clamped; tail values discarded)
        const int tp = (t + 2 < TT) ? (t + 2) : (TT - 1);
        const float epre = __ldg(&em[(tp * BB + b) * KK + j]);
        const float mpre = __ldg(&mask[tp * BB + b]);

        // matvec: S = sum_i u_prev[i] * E[i][j]; 4 independent acc chains
        const __nv_bfloat162 z2 = __float2bfloat162_rn(0.0f);
        __nv_bfloat162 a0 = z2, a1 = z2, a2 = z2, a3 = z2;
#pragma unroll
        for (int k = 0; k < KK / 8; k++) {
            const uint4 q = *(const uint4*)&pv[r][8 * k];   // LDS.128 bcast: 8 i's
            a0 = __hfma2(epk[4 * k],     *(const __nv_bfloat162*)&q.x, a0);
            a1 = __hfma2(epk[4 * k + 1], *(const __nv_bfloat162*)&q.y, a1);
            a2 = __hfma2(epk[4 * k + 2], *(const __nv_bfloat162*)&q.z, a2);
            a3 = __hfma2(epk[4 * k + 3], *(const __nv_bfloat162*)&q.w, a3);
        }
        const __nv_bfloat162 s2 = __hadd2(__hadd2(a0, a1), __hadd2(a2, a3));
        const float S  = __low2float(s2) + __high2float(s2);
        const float un = ex * S;
        u = (mcur != 0.0f) ? un : u;

        // rotate prefetch pipeline
        ecur = enext;  mcur = mnext;
        enext = epre;  mnext = mpre;

        // exact power-of-2 rescale every 8 steps
        if ((t & 7) == 0) {
            float v = u;
            for (int o = 16; o; o >>= 1) v = fmaxf(v, __shfl_xor_sync(0xffffffffu, v, o));
            if (lane == 0) wred[warp] = v;
            __syncthreads();
            float m = fmaxf(fmaxf(wred[0], wred[1]), fmaxf(wred[2], wred[3]));
            int e   = ilogbf(m);
            float s = __int_as_float((unsigned)(127 - e) << 23);  // exact 2^-e
            u  *= s;
            Ce += e;
        }

        pv[w][j] = __float2bfloat16(u);
        __syncthreads();
    }

    // finalize: -logZ[b] = -(Ce*ln2 + log(sum_j u[j]*exp(end[j])))
    float z = u * __expf(endT[j]);
    for (int o = 16; o; o >>= 1) z += __shfl_xor_sync(0xffffffffu, z, o);
    if (lane == 0) wred[warp] = z;
    __syncthreads();
    if (j == 0) {
        float zsum  = wred[0] + wred[1] + wred[2] + wred[3];
        double logZ = (double)Ce * 0.6931471805599453 + log((double)zsum);
        g_negLogZ[b] = (float)(-logZ);
    }
}

// ---- gold-path score + final combine: one block per batch ----
__global__ void __launch_bounds__(128) path_kernel(
    const float* __restrict__ em, const int* __restrict__ tags,
    const float* __restrict__ mask, const float* __restrict__ startT,
    const float* __restrict__ trans, const float* __restrict__ endT,
    float* __restrict__ out)
{
    __shared__ float sacc[4], smsum[4];
    const int b = blockIdx.x, tid = threadIdx.x, warp = tid >> 5, lane = tid & 31;
    float acc = 0.0f, msum = 0.0f;
    for (int t = tid; t < TT; t += 128) {
        int   tg = tags[t * BB + b];
        float m  = mask[t * BB + b];
        acc  += em[(t * BB + b) * KK + tg] * m;
        msum += m;
        if (t > 0) {
            int tp = tags[(t - 1) * BB + b];
            acc += trans[tp * KK + tg] * m;
        }
    }
    for (int o = 16; o; o >>= 1) {
        acc  += __shfl_xor_sync(0xffffffffu, acc, o);
        msum += __shfl_xor_sync(0xffffffffu, msum, o);
    }
    if (lane == 0) { sacc[warp] = acc; smsum[warp] = msum; }
    __syncthreads();
    if (tid == 0) {
        float a  = sacc[0] + sacc[1] + sacc[2] + sacc[3];
        float ms = smsum[0] + smsum[1] + smsum[2] + smsum[3];
        int cnt = (int)(ms + 0.5f); if (cnt < 1) cnt = 1;
        a += startT[tags[b]] + endT[tags[(cnt - 1) * BB + b]];
        atomicAdd(out, a + g_negLogZ[b]);
    }
}

extern "C" void kernel_launch(void* const* d_in, const int* in_sizes, int n_in,
                              void* d_out, int out_size) {
    const float* em     = (const float*)d_in[0];
    const int*   tags   = (const int*)  d_in[1];
    const float* mask   = (const float*)d_in[2];
    const float* startT = (const float*)d_in[3];
    const float* trans  = (const float*)d_in[4];
    const float* endT   = (const float*)d_in[5];
    float* out = (float*)d_out;

    crf_fwd_kernel<<<BB, KK>>>(em, mask, startT, trans, endT, out);
    path_kernel<<<BB, 128>>>(em, tags, mask, startT, trans, endT, out);
}

// round 14
// speedup vs baseline: 1.0347x; 1.0347x over previous
#include <cuda_runtime.h>
#include <math.h>

#define TT 1024
#define BB 512
#define KK 128
#define GG 2   // batches per block

__device__ float g_path[BB];   // gold-path score per batch (path writes, fwd reads)

// ---- gold-path score: one block per batch. Runs FIRST; block 0 zeroes out. ----
__global__ void __launch_bounds__(128) path_kernel(
    const float* __restrict__ em, const int* __restrict__ tags,
    const float* __restrict__ mask, const float* __restrict__ startT,
    const float* __restrict__ trans, const float* __restrict__ endT,
    float* __restrict__ out)
{
    __shared__ float sacc[4], smsum[4];
    const int b = blockIdx.x, tid = threadIdx.x, warp = tid >> 5, lane = tid & 31;
    if (b == 0 && tid == 0) out[0] = 0.0f;   // safe: only fwd (later kernel) writes out
    float acc = 0.0f, msum = 0.0f;
    for (int t = tid; t < TT; t += 128) {
        int   tg = tags[t * BB + b];
        float m  = mask[t * BB + b];
        acc  += em[(t * BB + b) * KK + tg] * m;
        msum += m;
        if (t > 0) {
            int tp = tags[(t - 1) * BB + b];
            acc += trans[tp * KK + tg] * m;
        }
    }
    for (int o = 16; o; o >>= 1) {
        acc  += __shfl_xor_sync(0xffffffffu, acc, o);
        msum += __shfl_xor_sync(0xffffffffu, msum, o);
    }
    if (lane == 0) { sacc[warp] = acc; smsum[warp] = msum; }
    __syncthreads();
    if (tid == 0) {
        float a  = sacc[0] + sacc[1] + sacc[2] + sacc[3];
        float ms = smsum[0] + smsum[1] + smsum[2] + smsum[3];
        int cnt = (int)(ms + 0.5f); if (cnt < 1) cnt = 1;
        a += startT[tags[b]] + endT[tags[(cnt - 1) * BB + b]];
        g_path[b] = a;
    }
}

// ---- forward recurrence: scaled linear domain, int8 DP4A residual matvec ----
// S_j = sum_i u_i + sum_i R_ij u_i,  R = exp(trans)-1, per-warp dynamic quantization.
// grid = BB/GG = 256 blocks, 128 threads, 2 CTAs/SM.
__global__ void __launch_bounds__(128, 2) crf_fwd_kernel(
    const float* __restrict__ em,      // [T,B,K]
    const float* __restrict__ mask,    // [T,B]
    const float* __restrict__ startT,  // [K]
    const float* __restrict__ trans,   // [K,K]
    const float* __restrict__ endT,    // [K]
    float* __restrict__ out)
{
    __shared__ alignas(16) int    squ[2][GG][KK / 4];   // packed int8 state (u quantized)
    __shared__ alignas(16) float4 spub[2][GG][2];       // {base0,sU0,base1,sU1},{base2,sU2,base3,sU3}
    __shared__ float wred[4][GG];
    __shared__ float sws[4];

    const int j    = threadIdx.x;   // tag column / state index i owned by this thread
    const int warp = j >> 5;
    const int lane = j & 31;
    const int b0   = blockIdx.x * GG;

    // ---- init: global |R| max (computed identically in every CTA) ----
    float rmax = 0.0f;
    for (int i = 0; i < KK; i++) {
        float R = __expf(trans[i * KK + j]) - 1.0f;
        rmax = fmaxf(rmax, fabsf(R));
    }
    rmax = __uint_as_float(__reduce_max_sync(0xffffffffu, __float_as_uint(rmax)));
    if (lane == 0) sws[warp] = rmax;
    __syncthreads();
    rmax = fmaxf(fmaxf(sws[0], sws[1]), fmaxf(sws[2], sws[3]));
    rmax = fmaxf(rmax, 1e-20f);
    const float sR    = rmax * (1.0f / 127.0f);
    const float invSR = 127.0f / rmax;

    // residual column packed as int8: rq4[m] holds i = 4m..4m+3
    int rq4[KK / 4];
#pragma unroll
    for (int m = 0; m < KK / 4; m++) {
        int q0 = __float2int_rn((__expf(trans[(4 * m + 0) * KK + j]) - 1.0f) * invSR);
        int q1 = __float2int_rn((__expf(trans[(4 * m + 1) * KK + j]) - 1.0f) * invSR);
        int q2 = __float2int_rn((__expf(trans[(4 * m + 2) * KK + j]) - 1.0f) * invSR);
        int q3 = __float2int_rn((__expf(trans[(4 * m + 3) * KK + j]) - 1.0f) * invSR);
        rq4[m] = (q0 & 255) | ((q1 & 255) << 8) | ((q2 & 255) << 16) | ((q3 & 255) << 24);
    }

    float u[GG];    // fp32 master state
    int   Ce[GG];   // exact power-of-2 scale exponent
    const float sj = startT[j];
#pragma unroll
    for (int g = 0; g < GG; g++) {
        u[g]  = __expf(sj + em[(b0 + g) * KK + j]);
        Ce[g] = 0;
    }

    // quantize + publish state into buffer 1 (read at t=1)
#pragma unroll
    for (int g = 0; g < GG; g++) {
        float wmax = __uint_as_float(__reduce_max_sync(0xffffffffu, __float_as_uint(u[g])));
        wmax = fmaxf(wmax, 1e-30f);
        float qs = __fdividef(127.0f, wmax);
        int qu = __float2int_rn(u[g] * qs); qu = min(qu, 127);
        int sumq = __reduce_add_sync(0xffffffffu, qu);
        ((unsigned char*)&squ[1][g][0])[j] = (unsigned char)qu;
        if (lane == 0) {
            float sU = wmax * (1.0f / 127.0f);
            ((float2*)&spub[1][g][0])[warp] = make_float2(sU * (float)sumq, sU);
        }
    }
    __syncthreads();

    // 2-deep register prefetch pipeline for em/mask
    float ecur[GG], enext[GG], mcur[GG], mnext[GG];
#pragma unroll
    for (int g = 0; g < GG; g++) {
        ecur[g]  = __ldg(&em[(1 * BB + b0 + g) * KK + j]);
        mcur[g]  = __ldg(&mask[1 * BB + b0 + g]);
        enext[g] = __ldg(&em[(2 * BB + b0 + g) * KK + j]);
        mnext[g] = __ldg(&mask[2 * BB + b0 + g]);
    }

    for (int t = 1; t < TT; t++) {
        const int r = t & 1, w = r ^ 1;

        // exp(em) early: MUFU latency hides under the matvec
        float ex[GG];
#pragma unroll
        for (int g = 0; g < GG; g++) ex[g] = __expf(ecur[g]);

        // kick off loads for t+2 (clamped; tail values discarded)
        const int tp = (t + 2 < TT) ? (t + 2) : (TT - 1);
        float epre[GG], mpre[GG];
#pragma unroll
        for (int g = 0; g < GG; g++) {
            epre[g] = __ldg(&em[(tp * BB + b0 + g) * KK + j]);
            mpre[g] = __ldg(&mask[tp * BB + b0 + g]);
        }

        // int8 residual matvec: 4 acc chains per batch (one per warp-group of i)
#pragma unroll
        for (int g = 0; g < GG; g++) {
            const uint4* qp = (const uint4*)&squ[r][g][0];   // 8 x uint4 (16 int8 each)
            int a0 = 0, a1 = 0, a2 = 0, a3 = 0;
#pragma unroll
            for (int k = 0; k < 2; k++) {    // warp-groups 0..3, 2 uint4 each
                uint4 Q;
                Q = qp[0 * 2 + k];
                a0 = __dp4a(rq4[(0 * 2 + k) * 4 + 0], (int)Q.x, a0);
                a0 = __dp4a(rq4[(0 * 2 + k) * 4 + 1], (int)Q.y, a0);
                a0 = __dp4a(rq4[(0 * 2 + k) * 4 + 2], (int)Q.z, a0);
                a0 = __dp4a(rq4[(0 * 2 + k) * 4 + 3], (int)Q.w, a0);
                Q = qp[1 * 2 + k];
                a1 = __dp4a(rq4[(1 * 2 + k) * 4 + 0], (int)Q.x, a1);
                a1 = __dp4a(rq4[(1 * 2 + k) * 4 + 1], (int)Q.y, a1);
                a1 = __dp4a(rq4[(1 * 2 + k) * 4 + 2], (int)Q.z, a1);
                a1 = __dp4a(rq4[(1 * 2 + k) * 4 + 3], (int)Q.w, a1);
                Q = qp[2 * 2 + k];
                a2 = __dp4a(rq4[(2 * 2 + k) * 4 + 0], (int)Q.x, a2);
                a2 = __dp4a(rq4[(2 * 2 + k) * 4 + 1], (int)Q.y, a2);
                a2 = __dp4a(rq4[(2 * 2 + k) * 4 + 2], (int)Q.z, a2);
                a2 = __dp4a(rq4[(2 * 2 + k) * 4 + 3], (int)Q.w, a2);
                Q = qp[3 * 2 + k];
                a3 = __dp4a(rq4[(3 * 2 + k) * 4 + 0], (int)Q.x, a3);
                a3 = __dp4a(rq4[(3 * 2 + k) * 4 + 1], (int)Q.y, a3);
                a3 = __dp4a(rq4[(3 * 2 + k) * 4 + 2], (int)Q.z, a3);
                a3 = __dp4a(rq4[(3 * 2 + k) * 4 + 3], (int)Q.w, a3);
            }
            const float4 pA = spub[r][g][0];
            const float4 pB = spub[r][g][1];
            const float Bsum = (pA.x + pA.z) + (pB.x + pB.z);
            const float D = pA.y * (float)a0 + pA.w * (float)a1
                          + pB.y * (float)a2 + pB.w * (float)a3;
            const float S  = fmaf(sR, D, Bsum);
            const float un = ex[g] * S;
            u[g] = (mcur[g] != 0.0f) ? un : u[g];
        }

        // rotate prefetch pipeline
#pragma unroll
        for (int g = 0; g < GG; g++) {
            ecur[g]  = enext[g];  mcur[g]  = mnext[g];
            enext[g] = epre[g];   mnext[g] = mpre[g];
        }

        // exact power-of-2 rescale every 8 steps
        if ((t & 7) == 0) {
#pragma unroll
            for (int g = 0; g < GG; g++) {
                float v = __uint_as_float(__reduce_max_sync(0xffffffffu, __float_as_uint(u[g])));
                if (lane == 0) wred[warp][g] = v;
            }
            __syncthreads();
#pragma unroll
            for (int g = 0; g < GG; g++) {
                float m = fmaxf(fmaxf(wred[0][g], wred[1][g]),
                                fmaxf(wred[2][g], wred[3][g]));
                int e   = ilogbf(m);
                float s = __int_as_float((unsigned)(127 - e) << 23);  // exact 2^-e
                u[g]  *= s;
                Ce[g] += e;
            }
        }

        // quantize + publish next-state (per-warp scale; no extra barrier)
#pragma unroll
        for (int g = 0; g < GG; g++) {
            float wmax = __uint_as_float(__reduce_max_sync(0xffffffffu, __float_as_uint(u[g])));
            wmax = fmaxf(wmax, 1e-30f);
            float qs = __fdividef(127.0f, wmax);
            int qu = __float2int_rn(u[g] * qs); qu = min(qu, 127);
            int sumq = __reduce_add_sync(0xffffffffu, qu);
            ((unsigned char*)&squ[w][g][0])[j] = (unsigned char)qu;
            if (lane == 0) {
                float sU = wmax * (1.0f / 127.0f);
                ((float2*)&spub[w][g][0])[warp] = make_float2(sU * (float)sumq, sU);
            }
        }
        __syncthreads();
    }

    // finalize: -logZ[b] = -(Ce*ln2 + log(sum_j u[j]*exp(end[j])))
    const float ezj = __expf(endT[j]);
#pragma unroll
    for (int g = 0; g < GG; g++) {
        float z = u[g] * ezj;
        for (int o = 16; o; o >>= 1) z += __shfl_xor_sync(0xffffffffu, z, o);
        if (lane == 0) wred[warp][g] = z;
    }
    __syncthreads();
    if (j < GG) {
        const int g = j;
        float zsum  = wred[0][g] + wred[1][g] + wred[2][g] + wred[3][g];
        double logZ = (double)Ce[g] * 0.6931471805599453 + log((double)zsum);
        atomicAdd(out, g_path[b0 + g] + (float)(-logZ));
    }
}

extern "C" void kernel_launch(void* const* d_in, const int* in_sizes, int n_in,
                              void* d_out, int out_size) {
    const float* em     = (const float*)d_in[0];
    const int*   tags   = (const int*)  d_in[1];
    const float* mask   = (const float*)d_in[2];
    const float* startT = (const float*)d_in[3];
    const float* trans  = (const float*)d_in[4];
    const float* endT   = (const float*)d_in[5];
    float* out = (float*)d_out;

    path_kernel<<<BB, 128>>>(em, tags, mask, startT, trans, endT, out);
    crf_fwd_kernel<<<BB / GG, KK>>>(em, mask, startT, trans, endT, out);
}